// round 14
// baseline (speedup 1.0000x reference)
#include <cuda_runtime.h>
#include <cuda_bf16.h>
#include <cstdint>
#include <cstddef>

// Problem constants
#define B_  32
#define S_  2048
#define F_  512
#define MOMENTUM 0.1f
#define EPS 1e-5f

typedef __nv_bfloat16 bf16;

// ---------------- device scratch (static, no allocations) ----------------
// GEMM operands live as bf16 hi/lo pairs in NATURAL row-major layout.
__device__ bf16  g_xnh [(size_t)B_ * S_ * F_];
__device__ bf16  g_xnl [(size_t)B_ * S_ * F_];
__device__ bf16  g_xTh [(size_t)B_ * F_ * S_];
__device__ bf16  g_xTl [(size_t)B_ * F_ * S_];
__device__ float g_sig [(size_t)B_ * F_ * F_];   // fp32 (trace / blend / initp)
__device__ bf16  g_sigh[(size_t)B_ * F_ * F_];
__device__ bf16  g_sigl[(size_t)B_ * F_ * F_];
__device__ bf16  g_Ph  [(size_t)B_ * F_ * F_];
__device__ bf16  g_Pl  [(size_t)B_ * F_ * F_];
__device__ bf16  g_Qh  [(size_t)B_ * F_ * F_];
__device__ bf16  g_Ql  [(size_t)B_ * F_ * F_];
__device__ bf16  g_T1h [(size_t)B_ * F_ * F_];
__device__ bf16  g_T1l [(size_t)B_ * F_ * F_];
__device__ bf16  g_T2h [(size_t)B_ * F_ * F_];
__device__ bf16  g_T2l [(size_t)B_ * F_ * F_];
__device__ float g_mean [B_ * F_];
__device__ float g_invtr[B_];
__device__ float g_rstr [B_];

// ---------------- helpers ----------------
__device__ __forceinline__ void split_bf16(float x, bf16& h, bf16& l) {
    h = __float2bfloat16_rn(x);
    l = __float2bfloat16_rn(x - __bfloat162float(h));
}
__device__ __forceinline__ void split2_store(bf16* ph, bf16* pl, float v0, float v1) {
    bf16 h0, l0, h1, l1;
    split_bf16(v0, h0, l0);
    split_bf16(v1, h1, l1);
    *(__nv_bfloat162*)ph = __halves2bfloat162(h0, h1);
    *(__nv_bfloat162*)pl = __halves2bfloat162(l0, l1);
}
__device__ __forceinline__ void cp_async16(void* smem_dst, const void* gmem_src) {
    uint32_t s = (uint32_t)__cvta_generic_to_shared(smem_dst);
    asm volatile("cp.async.cg.shared.global [%0], [%1], 16;\n" :: "r"(s), "l"(gmem_src));
}
#define CP_COMMIT asm volatile("cp.async.commit_group;" ::: "memory")
#define CP_WAIT1  asm volatile("cp.async.wait_group 1;"  ::: "memory")
#define CP_WAIT0  asm volatile("cp.async.wait_group 0;"  ::: "memory")

__device__ __forceinline__ void mma_bf16(float* c, const uint32_t* a, const uint32_t* b) {
    asm volatile(
        "mma.sync.aligned.m16n8k16.row.col.f32.bf16.bf16.f32 "
        "{%0,%1,%2,%3}, {%4,%5,%6,%7}, {%8,%9}, {%0,%1,%2,%3};"
        : "+f"(c[0]), "+f"(c[1]), "+f"(c[2]), "+f"(c[3])
        : "r"(a[0]), "r"(a[1]), "r"(a[2]), "r"(a[3]), "r"(b[0]), "r"(b[1]));
}

// ---------------- elementwise kernels ----------------
__global__ void mean_kernel(const float* __restrict__ x,
                            const float* __restrict__ rm,
                            float* __restrict__ mean) {
    int b = blockIdx.x;
    int f = threadIdx.x;
    const float* xb = x + (size_t)b * S_ * F_ + f;
    float acc = 0.f;
    #pragma unroll 8
    for (int s = 0; s < S_; s++) acc += xb[(size_t)s * F_];
    mean[b * F_ + f] = (1.f - MOMENTUM) * rm[f] + MOMENTUM * (acc * (1.f / (float)S_));
}

// center + split; write xn hi/lo and xnT hi/lo (32x32 tiles, bf162 stores)
__global__ void ct_kernel(const float* __restrict__ x,
                          const float* __restrict__ mean,
                          bf16* __restrict__ xnh, bf16* __restrict__ xnl,
                          bf16* __restrict__ xTh, bf16* __restrict__ xTl) {
    __shared__ float t[32][33];
    int b = blockIdx.z;
    int s0 = blockIdx.x * 32, f0 = blockIdx.y * 32;
    int tx = threadIdx.x;   // 0..15 -> col pair
    int ty = threadIdx.y;   // 0..15 -> row (two passes)
    const float* xb = x + (size_t)b * S_ * F_;
    float m0 = mean[b * F_ + f0 + 2 * tx];
    float m1 = mean[b * F_ + f0 + 2 * tx + 1];
    size_t bo = (size_t)b * S_ * F_;
    #pragma unroll
    for (int i = 0; i < 2; i++) {
        int row = ty + i * 16;
        int s = s0 + row;
        float v0 = xb[(size_t)s * F_ + f0 + 2 * tx]     - m0;
        float v1 = xb[(size_t)s * F_ + f0 + 2 * tx + 1] - m1;
        t[row][2 * tx] = v0;
        t[row][2 * tx + 1] = v1;
        size_t o = bo + (size_t)s * F_ + f0 + 2 * tx;
        split2_store(xnh + o, xnl + o, v0, v1);
    }
    __syncthreads();
    size_t bt = (size_t)b * F_ * S_;
    #pragma unroll
    for (int i = 0; i < 2; i++) {
        int frow = ty + i * 16;
        int f = f0 + frow;
        float v0 = t[2 * tx][frow];
        float v1 = t[2 * tx + 1][frow];
        size_t o = bt + (size_t)f * S_ + s0 + 2 * tx;
        split2_store(xTh + o, xTl + o, v0, v1);
    }
}

__global__ void trace_kernel(const float* __restrict__ sigma,
                             float* __restrict__ invtr,
                             float* __restrict__ rstr) {
    __shared__ float red[512];
    int b = blockIdx.x, t = threadIdx.x;
    red[t] = sigma[(size_t)b * F_ * F_ + (size_t)t * (F_ + 1)];
    __syncthreads();
    for (int s = 256; s > 0; s >>= 1) {
        if (t < s) red[t] += red[t + s];
        __syncthreads();
    }
    if (t == 0) {
        float tr = red[0];
        invtr[b] = 1.f / tr;
        rstr[b]  = 1.f / sqrtf(tr);
    }
}

// P1 = 1.5I - 0.5 sigma/tr  -> hi/lo natural layout (each thread: 2 cols)
__global__ void initp_kernel(const float* __restrict__ sigma,
                             const float* __restrict__ invtr,
                             bf16* __restrict__ Ph, bf16* __restrict__ Pl) {
    size_t pidx = (size_t)blockIdx.x * blockDim.x + threadIdx.x;   // pair index
    size_t idx = pidx * 2;
    int b = (int)(idx >> 18);
    int r = (int)((idx >> 9) & (F_ - 1));
    int c = (int)(idx & (F_ - 1));
    float it = invtr[b];
    float v0 = -0.5f * it * sigma[idx];
    float v1 = -0.5f * it * sigma[idx + 1];
    if (r == c)     v0 += 1.5f;
    if (r == c + 1) v1 += 1.5f;
    split2_store(Ph + idx, Pl + idx, v0, v1);
}

// ---------------- bf16x3 GEMM, pre-split natural-layout operands ----------------
// C = A * B^T : both operand tiles are 128 rows x 32 k, rows along K.
// All B matrices symmetric (or xnT for SYRK) => computes A@B as desired.
// mode 0: C = AB                       (write hi/lo)
// mode 1: C = 1.5*D - 0.5*scale[b]*AB  (D hi/lo reconstruct; write hi/lo)
// mode 2: C = scale[b]*AB              (write fp32)
// mode 3: C = 0.9*E + 0.1*(AB/(S-1)+eps*I)  (write fp32 + hi/lo; E no batch stride)
// smem: Ah/Al/Bh/Bl each [128][40] bf16 (80 B rows) = 10240 B -> 40960 B/stage, x2.
#define STREAM_B 10240
#define STAGE_B  40960
#define GEMM_SMEM_TOTAL (2 * STAGE_B)   // 81920

template<int TRI>
__global__ __launch_bounds__(256, 2) void gemm_bf16_kernel(
        const bf16* __restrict__ Agh, const bf16* __restrict__ Agl,
        const bf16* __restrict__ Bgh, const bf16* __restrict__ Bgl,
        float* __restrict__ Cf,
        bf16* __restrict__ Cgh, bf16* __restrict__ Cgl,
        const bf16* __restrict__ Dgh, const bf16* __restrict__ Dgl,
        const float* __restrict__ Ef, const float* __restrict__ scale,
        int K, int mode, size_t sAb, size_t sBb, size_t sCb) {
    extern __shared__ char smem[];

    int bz = blockIdx.z;
    const bf16* Ah = Agh + (size_t)bz * sAb;
    const bf16* Al = Agl + (size_t)bz * sAb;
    const bf16* Bh = Bgh + (size_t)bz * sBb;
    const bf16* Bl = Bgl + (size_t)bz * sBb;

    int m0, n0;
    bool mirror = false;
    if (TRI) {
        int t = blockIdx.x;   // 0..9
        int bi = (t < 4) ? 0 : (t < 7) ? 1 : (t < 9) ? 2 : 3;
        int start = (bi == 0) ? 0 : (bi == 1) ? 4 : (bi == 2) ? 7 : 9;
        int bj = bi + (t - start);
        m0 = bi * 128; n0 = bj * 128;
        mirror = (bi != bj);
    } else {
        m0 = blockIdx.y * 128;
        n0 = blockIdx.x * 128;
    }

    int tid  = threadIdx.x;
    int lane = tid & 31;
    int wid  = tid >> 5;
    int warp_m = (wid >> 2) * 64;
    int warp_n = (wid & 3) * 32;
    int g  = lane >> 2;
    int tg = lane & 3;

    float acc[4][4][4];
    #pragma unroll
    for (int i = 0; i < 4; i++)
        #pragma unroll
        for (int j = 0; j < 4; j++)
            #pragma unroll
            for (int q = 0; q < 4; q++) acc[i][j][q] = 0.f;

    const bf16* gsrc[4] = { Ah + (size_t)m0 * K, Al + (size_t)m0 * K,
                            Bh + (size_t)n0 * K, Bl + (size_t)n0 * K };
    // 4 streams x 128 rows x 64 B; 16B chunks: 2048 chunks / 256 thr = 8/thread
    auto prefetch = [&](int st, int k0) {
        char* base = smem + st * STAGE_B;
        #pragma unroll
        for (int sm = 0; sm < 4; sm++) {
            #pragma unroll
            for (int q = 0; q < 2; q++) {
                int ch = tid * 2 + q;       // 0..511
                int row = ch >> 2;
                int o = ch & 3;
                cp_async16(base + sm * STREAM_B + row * 80 + o * 16,
                           gsrc[sm] + (size_t)row * K + k0 + o * 8);
            }
        }
    };

    prefetch(0, 0);
    CP_COMMIT;

    const int NC = K >> 5;
    for (int c = 0; c < NC; c++) {
        int bsel = c & 1;
        __syncthreads();   // all warps done with mainloop(c-1): buf (c+1)&1 free
        if (c + 1 < NC) {
            prefetch(bsel ^ 1, (c + 1) * 32);
            CP_COMMIT;
            CP_WAIT1;
        } else {
            CP_WAIT0;
        }
        __syncthreads();   // chunk c visible to all warps

        const char* st = smem + bsel * STAGE_B;
        const char* sAh = st;
        const char* sAl = st + STREAM_B;
        const char* sBh = st + 2 * STREAM_B;
        const char* sBl = st + 3 * STREAM_B;

        #pragma unroll
        for (int kk = 0; kk < 32; kk += 16) {
            int kf = kk + 2 * tg;
            uint32_t bh[4][2], bl[4][2];
            #pragma unroll
            for (int j = 0; j < 4; j++) {
                int col = warp_n + j * 8 + g;
                bh[j][0] = *(const uint32_t*)(sBh + (size_t)(col * 40 + kf) * 2);
                bh[j][1] = *(const uint32_t*)(sBh + (size_t)(col * 40 + kf + 8) * 2);
                bl[j][0] = *(const uint32_t*)(sBl + (size_t)(col * 40 + kf) * 2);
                bl[j][1] = *(const uint32_t*)(sBl + (size_t)(col * 40 + kf + 8) * 2);
            }
            #pragma unroll
            for (int i = 0; i < 4; i++) {
                int row = warp_m + i * 16;
                uint32_t ah[4], al[4];
                ah[0] = *(const uint32_t*)(sAh + (size_t)((row + g) * 40 + kf) * 2);
                ah[1] = *(const uint32_t*)(sAh + (size_t)((row + g + 8) * 40 + kf) * 2);
                ah[2] = *(const uint32_t*)(sAh + (size_t)((row + g) * 40 + kf + 8) * 2);
                ah[3] = *(const uint32_t*)(sAh + (size_t)((row + g + 8) * 40 + kf + 8) * 2);
                al[0] = *(const uint32_t*)(sAl + (size_t)((row + g) * 40 + kf) * 2);
                al[1] = *(const uint32_t*)(sAl + (size_t)((row + g + 8) * 40 + kf) * 2);
                al[2] = *(const uint32_t*)(sAl + (size_t)((row + g) * 40 + kf + 8) * 2);
                al[3] = *(const uint32_t*)(sAl + (size_t)((row + g + 8) * 40 + kf + 8) * 2);
                #pragma unroll
                for (int j = 0; j < 4; j++) {
                    mma_bf16(acc[i][j], ah, bh[j]);   // hi*hi
                    mma_bf16(acc[i][j], ah, bl[j]);   // hi*lo
                    mma_bf16(acc[i][j], al, bh[j]);   // lo*hi
                }
            }
        }
    }

    // ---- epilogue ----
    float sc = 0.f;
    if (mode == 1) sc = -0.5f * scale[bz];
    else if (mode == 2) sc = scale[bz];
    const bf16* Dh = (mode == 1) ? (Dgh + (size_t)bz * sCb) : nullptr;
    const bf16* Dl = (mode == 1) ? (Dgl + (size_t)bz * sCb) : nullptr;
    float* Cfp = (mode >= 2) ? (Cf + (size_t)bz * sCb) : nullptr;
    bf16* Ch = (mode != 2) ? (Cgh + (size_t)bz * sCb) : nullptr;
    bf16* Cl = (mode != 2) ? (Cgl + (size_t)bz * sCb) : nullptr;
    const float inv_nm1 = 1.f / (float)(S_ - 1);

    #pragma unroll
    for (int i = 0; i < 4; i++) {
        #pragma unroll
        for (int j = 0; j < 4; j++) {
            int r0 = m0 + warp_m + i * 16 + g;
            int c0 = n0 + warp_n + j * 8 + 2 * tg;
            #pragma unroll
            for (int half = 0; half < 2; half++) {
                int r = r0 + half * 8;
                float v0 = acc[i][j][half * 2 + 0];
                float v1 = acc[i][j][half * 2 + 1];
                size_t off = (size_t)r * F_ + c0;
                float o0, o1;
                if (mode == 0) {
                    o0 = v0; o1 = v1;
                } else if (mode == 1) {
                    float d0 = __bfloat162float(Dh[off]) + __bfloat162float(Dl[off]);
                    float d1 = __bfloat162float(Dh[off + 1]) + __bfloat162float(Dl[off + 1]);
                    o0 = 1.5f * d0 + sc * v0;
                    o1 = 1.5f * d1 + sc * v1;
                } else if (mode == 2) {
                    o0 = sc * v0; o1 = sc * v1;
                } else {
                    float s0 = v0 * inv_nm1 + ((r == c0)     ? EPS : 0.f);
                    float s1 = v1 * inv_nm1 + ((r == c0 + 1) ? EPS : 0.f);
                    o0 = (1.f - MOMENTUM) * Ef[off] + MOMENTUM * s0;
                    o1 = (1.f - MOMENTUM) * Ef[off + 1] + MOMENTUM * s1;
                }
                if (mode >= 2) {
                    *(float2*)(Cfp + off) = make_float2(o0, o1);
                    if (TRI && mirror && mode == 3) {
                        Cfp[(size_t)c0 * F_ + r]       = o0;
                        Cfp[(size_t)(c0 + 1) * F_ + r] = o1;
                    }
                }
                if (mode != 2) {
                    split2_store(Ch + off, Cl + off, o0, o1);
                    if (TRI && mirror) {
                        bf16 h0, l0, h1, l1;
                        split_bf16(o0, h0, l0);
                        split_bf16(o1, h1, l1);
                        Ch[(size_t)c0 * F_ + r] = h0;
                        Cl[(size_t)c0 * F_ + r] = l0;
                        Ch[(size_t)(c0 + 1) * F_ + r] = h1;
                        Cl[(size_t)(c0 + 1) * F_ + r] = l1;
                    }
                }
            }
        }
    }
}

// ---------------- host launcher ----------------
extern "C" void kernel_launch(void* const* d_in, const int* in_sizes, int n_in,
                              void* d_out, int out_size) {
    const float* x  = (const float*)d_in[0];
    const float* rm = (const float*)d_in[1];
    const float* rc = (const float*)d_in[2];
    float* out = (float*)d_out;

    bf16 *xnh, *xnl, *xTh, *xTl, *sigh, *sigl, *Ph, *Pl, *Qh, *Ql, *T1h, *T1l, *T2h, *T2l;
    float *sig, *mean, *invtr, *rstr;
    cudaGetSymbolAddress((void**)&xnh,  g_xnh);
    cudaGetSymbolAddress((void**)&xnl,  g_xnl);
    cudaGetSymbolAddress((void**)&xTh,  g_xTh);
    cudaGetSymbolAddress((void**)&xTl,  g_xTl);
    cudaGetSymbolAddress((void**)&sig,  g_sig);
    cudaGetSymbolAddress((void**)&sigh, g_sigh);
    cudaGetSymbolAddress((void**)&sigl, g_sigl);
    cudaGetSymbolAddress((void**)&Ph,   g_Ph);
    cudaGetSymbolAddress((void**)&Pl,   g_Pl);
    cudaGetSymbolAddress((void**)&Qh,   g_Qh);
    cudaGetSymbolAddress((void**)&Ql,   g_Ql);
    cudaGetSymbolAddress((void**)&T1h,  g_T1h);
    cudaGetSymbolAddress((void**)&T1l,  g_T1l);
    cudaGetSymbolAddress((void**)&T2h,  g_T2h);
    cudaGetSymbolAddress((void**)&T2l,  g_T2l);
    cudaGetSymbolAddress((void**)&mean, g_mean);
    cudaGetSymbolAddress((void**)&invtr, g_invtr);
    cudaGetSymbolAddress((void**)&rstr, g_rstr);

    static bool attr_set = false;
    if (!attr_set) {
        cudaFuncSetAttribute(gemm_bf16_kernel<0>,
            cudaFuncAttributeMaxDynamicSharedMemorySize, GEMM_SMEM_TOTAL);
        cudaFuncSetAttribute(gemm_bf16_kernel<1>,
            cudaFuncAttributeMaxDynamicSharedMemorySize, GEMM_SMEM_TOTAL);
        attr_set = true;
    }

    const size_t FF = (size_t)F_ * F_;
    const size_t SF = (size_t)S_ * F_;

    // 1. blended mean
    mean_kernel<<<B_, F_>>>(x, rm, mean);
    // 2. center + split + transpose (bf16 hi/lo, natural layout)
    ct_kernel<<<dim3(S_ / 32, F_ / 32, B_), dim3(16, 16)>>>(x, mean, xnh, xnl, xTh, xTl);
    // 3. sigma (SYRK over xnT rows, K = S, triangular)
    gemm_bf16_kernel<1><<<dim3(10, 1, B_), 256, GEMM_SMEM_TOTAL>>>(
        xTh, xTl, xTh, xTl, sig, sigh, sigl, nullptr, nullptr, rc, nullptr,
        S_, 3, SF, SF, FF);
    // 4. trace
    trace_kernel<<<B_, F_>>>(sig, invtr, rstr);
    // 5. P1 = 1.5I - 0.5 sigma/tr
    initp_kernel<<<(unsigned)((size_t)B_ * FF / 2 / 256), 256>>>(sig, invtr, Ph, Pl);

    // 6. NS iterations 2..4 (all matrices symmetric)
    bf16 *Pih = Ph, *Pil = Pl, *Poh = Qh, *Pol = Ql;
    for (int it = 0; it < 3; it++) {
        gemm_bf16_kernel<1><<<dim3(10, 1, B_), 256, GEMM_SMEM_TOTAL>>>(
            Pih, Pil, Pih, Pil, nullptr, T1h, T1l, nullptr, nullptr, nullptr, nullptr,
            F_, 0, FF, FF, FF);
        gemm_bf16_kernel<1><<<dim3(10, 1, B_), 256, GEMM_SMEM_TOTAL>>>(
            T1h, T1l, Pih, Pil, nullptr, T2h, T2l, nullptr, nullptr, nullptr, nullptr,
            F_, 0, FF, FF, FF);
        gemm_bf16_kernel<1><<<dim3(10, 1, B_), 256, GEMM_SMEM_TOTAL>>>(
            T2h, T2l, sigh, sigl, nullptr, Poh, Pol, Pih, Pil, nullptr, invtr,
            F_, 1, FF, FF, FF);
        bf16* t;
        t = Pih; Pih = Poh; Poh = t;
        t = Pil; Pil = Pol; Pol = t;
    }

    // 7. out = (xn @ P3) * rsqrt(tr)
    gemm_bf16_kernel<0><<<dim3(4, 16, B_), 256, GEMM_SMEM_TOTAL>>>(
        xnh, xnl, Pih, Pil, out, nullptr, nullptr, nullptr, nullptr, nullptr, rstr,
        F_, 2, SF, FF, SF);
}

// round 15
// speedup vs baseline: 1.1372x; 1.1372x over previous
#include <cuda_runtime.h>
#include <cuda_bf16.h>
#include <cstdint>
#include <cstddef>

// Problem constants
#define B_  32
#define S_  2048
#define F_  512
#define MOMENTUM 0.1f
#define EPS 1e-5f

// ---------------- device scratch (static, no allocations) ----------------
__device__ float g_xn   [(size_t)B_ * S_ * F_];   // 128 MB  centered input
__device__ float g_sigma[(size_t)B_ * F_ * F_];
__device__ float g_P    [(size_t)B_ * F_ * F_];
__device__ float g_Q    [(size_t)B_ * F_ * F_];
__device__ float g_T1   [(size_t)B_ * F_ * F_];
__device__ float g_T2   [(size_t)B_ * F_ * F_];
__device__ float g_mean [B_ * F_];
__device__ float g_invtr[B_];
__device__ float g_rstr [B_];

// ---------------- elementwise kernels ----------------
__global__ void mean_kernel(const float* __restrict__ x,
                            const float* __restrict__ rm,
                            float* __restrict__ mean) {
    int b = blockIdx.x;
    int f = threadIdx.x;
    const float* xb = x + (size_t)b * S_ * F_ + f;
    float acc = 0.f;
    #pragma unroll 8
    for (int s = 0; s < S_; s++) acc += xb[(size_t)s * F_];
    mean[b * F_ + f] = (1.f - MOMENTUM) * rm[f] + MOMENTUM * (acc * (1.f / (float)S_));
}

__global__ void xn_kernel(const float* __restrict__ x,
                          const float* __restrict__ mean,
                          float* __restrict__ xn) {
    size_t p4 = (size_t)blockIdx.x * blockDim.x + threadIdx.x;
    size_t p  = p4 * 4;
    int b = (int)(p >> 20);            // S*F = 2^20
    int f = (int)(p & (F_ - 1));
    float4 xv = *(const float4*)(x + p);
    float4 mv = *(const float4*)(mean + b * F_ + f);
    float4 o;
    o.x = xv.x - mv.x; o.y = xv.y - mv.y; o.z = xv.z - mv.z; o.w = xv.w - mv.w;
    *(float4*)(xn + p) = o;
}

__global__ void trace_kernel(const float* __restrict__ sigma,
                             float* __restrict__ invtr,
                             float* __restrict__ rstr) {
    __shared__ float red[512];
    int b = blockIdx.x, t = threadIdx.x;
    red[t] = sigma[(size_t)b * F_ * F_ + (size_t)t * (F_ + 1)];
    __syncthreads();
    for (int s = 256; s > 0; s >>= 1) {
        if (t < s) red[t] += red[t + s];
        __syncthreads();
    }
    if (t == 0) {
        float tr = red[0];
        invtr[b] = 1.f / tr;
        rstr[b]  = 1.f / sqrtf(tr);
    }
}

__global__ void initp_kernel(const float* __restrict__ sigma,
                             const float* __restrict__ invtr,
                             float* __restrict__ P) {
    size_t idx = (size_t)blockIdx.x * blockDim.x + threadIdx.x;
    int b = (int)(idx >> 18);
    int r = (int)((idx >> 9) & (F_ - 1));
    int c = (int)(idx & (F_ - 1));
    float v = -0.5f * invtr[b] * sigma[idx];
    if (r == c) v += 1.5f;
    P[idx] = v;
}

// ---------------- helpers ----------------
__device__ __forceinline__ void cp_async16(void* smem_dst, const void* gmem_src) {
    uint32_t s = (uint32_t)__cvta_generic_to_shared(smem_dst);
    asm volatile("cp.async.cg.shared.global [%0], [%1], 16;\n" :: "r"(s), "l"(gmem_src));
}
#define CP_COMMIT asm volatile("cp.async.commit_group;" ::: "memory")
#define CP_WAIT0  asm volatile("cp.async.wait_group 0;"  ::: "memory")

__device__ __forceinline__ void split2_bf16(float x, float y, uint32_t& h, uint32_t& l) {
    __nv_bfloat16 hx = __float2bfloat16_rn(x);
    __nv_bfloat16 hy = __float2bfloat16_rn(y);
    float rx = x - __bfloat162float(hx);
    float ry = y - __bfloat162float(hy);
    __nv_bfloat16 lx = __float2bfloat16_rn(rx);
    __nv_bfloat16 ly = __float2bfloat16_rn(ry);
    __nv_bfloat162 hp = __halves2bfloat162(hx, hy);
    __nv_bfloat162 lp = __halves2bfloat162(lx, ly);
    h = *(uint32_t*)&hp;
    l = *(uint32_t*)&lp;
}

__device__ __forceinline__ void mma_bf16(float* c, const uint32_t* a, const uint32_t* b) {
    asm volatile(
        "mma.sync.aligned.m16n8k16.row.col.f32.bf16.bf16.f32 "
        "{%0,%1,%2,%3}, {%4,%5,%6,%7}, {%8,%9}, {%0,%1,%2,%3};"
        : "+f"(c[0]), "+f"(c[1]), "+f"(c[2]), "+f"(c[3])
        : "r"(a[0]), "r"(a[1]), "r"(a[2]), "r"(a[3]), "r"(b[0]), "r"(b[1]));
}

__device__ __forceinline__ void ldsm_x4(uint32_t& r0, uint32_t& r1, uint32_t& r2,
                                        uint32_t& r3, uint32_t addr) {
    asm volatile("ldmatrix.sync.aligned.m8n8.x4.shared.b16 {%0,%1,%2,%3}, [%4];"
                 : "=r"(r0), "=r"(r1), "=r"(r2), "=r"(r3) : "r"(addr));
}
__device__ __forceinline__ void ldsm_x2(uint32_t& r0, uint32_t& r1, uint32_t addr) {
    asm volatile("ldmatrix.sync.aligned.m8n8.x2.shared.b16 {%0,%1}, [%2];"
                 : "=r"(r0), "=r"(r1) : "r"(addr));
}

// ---------------- bf16x3 tensor-core GEMM ----------------
// R13 structure (single fp32 stage + convert + single bf16 stage, 76KB,
// 2 CTAs/SM) with (1) ldmatrix fragment loads in the mainloop and (2) an
// optional PAIR variant: blockIdx.x in [10,20) computes a second independent
// product A2*B2^T -> C2 (both mode 0, both triangular-symmetric).
// mode 0: C = AB
// mode 1: C = 1.5*D - 0.5*scale[b]*AB
// mode 2: C = scale[b]*AB
// mode 3: C = 0.9*E + 0.1*(AB/(S-1) + eps*I)   (E has no batch stride)
#define STG_FP32_B 36864
#define OFF_BF     STG_FP32_B                 // 36864
#define BF_STAGE_B 40960
#define GEMM_SMEM_TOTAL (OFF_BF + BF_STAGE_B) // 77824

template<int TRANSA, int TRI, int PAIR>
__global__ __launch_bounds__(256, 2) void gemm_bf16x3_kernel(
        const float* __restrict__ Ag, const float* __restrict__ Bg,
        float* __restrict__ Cg, const float* __restrict__ Dg,
        const float* __restrict__ Eg, const float* __restrict__ scale,
        int M, int N, int K, int mode,
        size_t sAb, size_t sBb, size_t sCb,
        const float* __restrict__ Ag2, const float* __restrict__ Bg2,
        float* __restrict__ Cg2) {
    extern __shared__ char smem[];

    int bz = blockIdx.z;
    int t = blockIdx.x;
    const float* Asel = Ag;
    const float* Bsel = Bg;
    float* Csel = Cg;
    if (PAIR && t >= 10) {
        t -= 10;
        Asel = Ag2; Bsel = Bg2; Csel = Cg2;
    }
    const float* A = Asel + (size_t)bz * sAb;
    const float* Bm = Bsel + (size_t)bz * sBb;
    float* C = Csel + (size_t)bz * sCb;

    int m0, n0;
    bool mirror = false;
    if (TRI) {
        int bi = (t < 4) ? 0 : (t < 7) ? 1 : (t < 9) ? 2 : 3;
        int start = (bi == 0) ? 0 : (bi == 1) ? 4 : (bi == 2) ? 7 : 9;
        int bj = bi + (t - start);
        m0 = bi * 128; n0 = bj * 128;
        mirror = (bi != bj);
    } else {
        m0 = blockIdx.y * 128;
        n0 = blockIdx.x * 128;
    }

    int tid  = threadIdx.x;
    int lane = tid & 31;
    int wid  = tid >> 5;
    int warp_m = (wid >> 2) * 64;     // 0 or 64
    int warp_n = (wid & 3) * 32;      // 0,32,64,96
    int g  = lane >> 2;               // 0..7
    int tg = lane & 3;                // 0..3

    float acc[4][4][4];
    #pragma unroll
    for (int i = 0; i < 4; i++)
        #pragma unroll
        for (int j = 0; j < 4; j++)
            #pragma unroll
            for (int q = 0; q < 4; q++) acc[i][j][q] = 0.f;

    // ---- cp.async staging of fp32 tiles (single stage) ----
    auto prefetch = [&](int k0) {
        float* sA = (float*)smem;
        float* sB = sA + 4608;
        if (!TRANSA) {
            #pragma unroll
            for (int p = 0; p < 4; p++) {
                int c = tid + p * 256;
                int m = c >> 3;
                int kc = (c & 7) * 4;
                cp_async16(sA + m * 36 + kc, A + (size_t)(m0 + m) * K + k0 + kc);
            }
        } else {
            #pragma unroll
            for (int p = 0; p < 4; p++) {
                int c = tid + p * 256;
                int k = c >> 5;
                int mc = (c & 31) * 4;
                cp_async16(sA + k * 132 + mc, A + (size_t)(k0 + k) * M + m0 + mc);
            }
        }
        #pragma unroll
        for (int p = 0; p < 4; p++) {
            int c = tid + p * 256;
            int k = c >> 5;
            int nc = (c & 31) * 4;
            cp_async16(sB + k * 132 + nc, Bm + (size_t)(k0 + k) * N + n0 + nc);
        }
    };

    prefetch(0);
    CP_COMMIT;

    const int NC = K >> 5;
    const int mrow = tid >> 1;             // 0..127
    const int ks   = (tid & 1) * 16;       // 0 or 16

    // ldmatrix lane base addresses (bytes, shared space)
    uint32_t sbf = (uint32_t)__cvta_generic_to_shared(smem + OFF_BF);
    uint32_t aoff = sbf + (uint32_t)(((warp_m + (lane & 15)) * 40 + (lane >> 4) * 8) * 2);
    uint32_t boff = sbf + 20480u + (uint32_t)(((warp_n + (lane & 7)) * 40 + ((lane >> 3) & 1) * 8) * 2);

    for (int c = 0; c < NC; c++) {
        CP_WAIT0;
        __syncthreads();   // fp32 stage ready; previous mainloop done

        // ---- convert: fp32 stage -> packed bf16 hi/lo (B transposed) ----
        {
            const float* fA = (const float*)smem;
            const float* fB = fA + 4608;
            char* bf = smem + OFF_BF;
            uint32_t* dAh = (uint32_t*)(bf +      0 + (size_t)(mrow * 40 + ks) * 2);
            uint32_t* dAl = (uint32_t*)(bf +  10240 + (size_t)(mrow * 40 + ks) * 2);
            uint32_t* dBh = (uint32_t*)(bf +  20480 + (size_t)(mrow * 40 + ks) * 2);
            uint32_t* dBl = (uint32_t*)(bf +  30720 + (size_t)(mrow * 40 + ks) * 2);
            if (!TRANSA) {
                const float* s = fA + mrow * 36 + ks;
                #pragma unroll
                for (int u = 0; u < 4; u++) {
                    float4 v = *(const float4*)(s + 4 * u);
                    uint32_t h0, l0, h1, l1;
                    split2_bf16(v.x, v.y, h0, l0);
                    split2_bf16(v.z, v.w, h1, l1);
                    dAh[2 * u] = h0; dAh[2 * u + 1] = h1;
                    dAl[2 * u] = l0; dAl[2 * u + 1] = l1;
                }
            } else {
                const float* s = fA + mrow;      // [k][132]
                #pragma unroll
                for (int u = 0; u < 8; u++) {
                    float v0 = s[(ks + 2 * u) * 132];
                    float v1 = s[(ks + 2 * u + 1) * 132];
                    uint32_t h, l;
                    split2_bf16(v0, v1, h, l);
                    dAh[u] = h; dAl[u] = l;
                }
            }
            const float* s = fB + mrow;          // [k][132], col = mrow (transpose)
            #pragma unroll
            for (int u = 0; u < 8; u++) {
                float v0 = s[(ks + 2 * u) * 132];
                float v1 = s[(ks + 2 * u + 1) * 132];
                uint32_t h, l;
                split2_bf16(v0, v1, h, l);
                dBh[u] = h; dBl[u] = l;
            }
        }
        __syncthreads();   // all convert reads of fp32 stage complete

        // issue next chunk's copies; they overlap the mainloop below
        if (c + 1 < NC) {
            prefetch((c + 1) * 32);
            CP_COMMIT;
        }

        // ---- mainloop: ldmatrix fragment loads + HMMA ----
        #pragma unroll
        for (int kk = 0; kk < 32; kk += 16) {
            uint32_t kb = (uint32_t)(kk * 2);
            uint32_t bh[4][2], bl[4][2];
            #pragma unroll
            for (int j = 0; j < 4; j++) {
                uint32_t ba = boff + (uint32_t)(j * 640) + kb;
                ldsm_x2(bh[j][0], bh[j][1], ba);
                ldsm_x2(bl[j][0], bl[j][1], ba + 10240u);
            }
            #pragma unroll
            for (int i = 0; i < 4; i++) {
                uint32_t aa = aoff + (uint32_t)(i * 1280) + kb;
                uint32_t ah[4], al[4];
                ldsm_x4(ah[0], ah[1], ah[2], ah[3], aa);
                ldsm_x4(al[0], al[1], al[2], al[3], aa + 10240u);
                #pragma unroll
                for (int j = 0; j < 4; j++) {
                    mma_bf16(acc[i][j], ah, bh[j]);   // hi*hi
                    mma_bf16(acc[i][j], ah, bl[j]);   // hi*lo
                    mma_bf16(acc[i][j], al, bh[j]);   // lo*hi
                }
            }
        }
    }

    // ---- epilogue ----
    float sc = 0.f;
    if (mode == 1) sc = -0.5f * scale[bz];
    else if (mode == 2) sc = scale[bz];
    const float* D = (mode == 1) ? (Dg + (size_t)bz * sCb) : nullptr;
    const float inv_nm1 = 1.f / (float)(S_ - 1);

    #pragma unroll
    for (int i = 0; i < 4; i++) {
        #pragma unroll
        for (int j = 0; j < 4; j++) {
            int r0 = m0 + warp_m + i * 16 + g;
            int c0 = n0 + warp_n + j * 8 + 2 * tg;
            #pragma unroll
            for (int half = 0; half < 2; half++) {
                int r = r0 + half * 8;
                float v0 = acc[i][j][half * 2 + 0];
                float v1 = acc[i][j][half * 2 + 1];
                size_t off = (size_t)r * N + c0;
                float2 o;
                if (mode == 0 || (PAIR && blockIdx.x >= 10)) {
                    o.x = v0; o.y = v1;
                } else if (mode == 1) {
                    o.x = 1.5f * D[off] + sc * v0;
                    o.y = 1.5f * D[off + 1] + sc * v1;
                } else if (mode == 2) {
                    o.x = sc * v0; o.y = sc * v1;
                } else {
                    float s0 = v0 * inv_nm1 + ((r == c0)     ? EPS : 0.f);
                    float s1 = v1 * inv_nm1 + ((r == c0 + 1) ? EPS : 0.f);
                    o.x = (1.f - MOMENTUM) * Eg[off] + MOMENTUM * s0;
                    o.y = (1.f - MOMENTUM) * Eg[off + 1] + MOMENTUM * s1;
                }
                *(float2*)(C + off) = o;
                if (TRI && mirror) {
                    C[(size_t)c0 * N + r]       = o.x;
                    C[(size_t)(c0 + 1) * N + r] = o.y;
                }
            }
        }
    }
}

// ---------------- host launcher ----------------
extern "C" void kernel_launch(void* const* d_in, const int* in_sizes, int n_in,
                              void* d_out, int out_size) {
    const float* x  = (const float*)d_in[0];
    const float* rm = (const float*)d_in[1];
    const float* rc = (const float*)d_in[2];
    float* out = (float*)d_out;

    float *xn, *sigma, *P, *Q, *T1, *T2, *mean, *invtr, *rstr;
    cudaGetSymbolAddress((void**)&xn,    g_xn);
    cudaGetSymbolAddress((void**)&sigma, g_sigma);
    cudaGetSymbolAddress((void**)&P,     g_P);
    cudaGetSymbolAddress((void**)&Q,     g_Q);
    cudaGetSymbolAddress((void**)&T1,    g_T1);
    cudaGetSymbolAddress((void**)&T2,    g_T2);
    cudaGetSymbolAddress((void**)&mean,  g_mean);
    cudaGetSymbolAddress((void**)&invtr, g_invtr);
    cudaGetSymbolAddress((void**)&rstr,  g_rstr);

    static bool attr_set = false;
    if (!attr_set) {
        cudaFuncSetAttribute(gemm_bf16x3_kernel<0,0,0>,
            cudaFuncAttributeMaxDynamicSharedMemorySize, GEMM_SMEM_TOTAL);
        cudaFuncSetAttribute(gemm_bf16x3_kernel<0,1,0>,
            cudaFuncAttributeMaxDynamicSharedMemorySize, GEMM_SMEM_TOTAL);
        cudaFuncSetAttribute(gemm_bf16x3_kernel<1,1,0>,
            cudaFuncAttributeMaxDynamicSharedMemorySize, GEMM_SMEM_TOTAL);
        cudaFuncSetAttribute(gemm_bf16x3_kernel<0,1,1>,
            cudaFuncAttributeMaxDynamicSharedMemorySize, GEMM_SMEM_TOTAL);
        attr_set = true;
    }

    const size_t FF = (size_t)F_ * F_;
    const size_t SF = (size_t)S_ * F_;

    // 1. blended mean
    mean_kernel<<<B_, F_>>>(x, rm, mean);
    // 2. xn = x - m
    xn_kernel<<<(unsigned)((size_t)B_ * SF / 4 / 256), 256>>>(x, mean, xn);
    // 3. sigma = 0.9*rc + 0.1*(xn^T xn /(S-1) + eps*I)  [transA SYRK, triangular]
    gemm_bf16x3_kernel<1,1,0><<<dim3(10, 1, B_), 256, GEMM_SMEM_TOTAL>>>(
        xn, xn, sigma, nullptr, rc, nullptr, F_, F_, S_, 3, SF, SF, FF,
        nullptr, nullptr, nullptr);
    // 4. trace
    trace_kernel<<<B_, F_>>>(sigma, invtr, rstr);
    // 5. P1 = 1.5I - 0.5 sigma/tr
    initp_kernel<<<(unsigned)((size_t)B_ * FF / 256), 256>>>(sigma, invtr, P);

    // 6. NS iterations 2..4:  P' = 1.5P - 0.5/tr * (P^2)*(P sigma)
    //    T1 = P*P and U(T2) = P*sigma are independent -> one paired launch.
    float* Pin = P;
    float* Pout = Q;
    for (int it = 0; it < 3; it++) {
        gemm_bf16x3_kernel<0,1,1><<<dim3(20, 1, B_), 256, GEMM_SMEM_TOTAL>>>(
            Pin, Pin, T1, nullptr, nullptr, nullptr, F_, F_, F_, 0, FF, FF, FF,
            Pin, sigma, T2);
        gemm_bf16x3_kernel<0,1,0><<<dim3(10, 1, B_), 256, GEMM_SMEM_TOTAL>>>(
            T1, T2, Pout, Pin, nullptr, invtr, F_, F_, F_, 1, FF, FF, FF,
            nullptr, nullptr, nullptr);
        float* tmp = Pin; Pin = Pout; Pout = tmp;
    }

    // 7. out = (xn @ P) * rsqrt(tr)
    gemm_bf16x3_kernel<0,0,0><<<dim3(4, 16, B_), 256, GEMM_SMEM_TOTAL>>>(
        xn, Pin, out, nullptr, nullptr, rstr, S_, F_, F_, 2, SF, FF, SF,
        nullptr, nullptr, nullptr);
}

// round 16
// speedup vs baseline: 1.2388x; 1.0893x over previous
#include <cuda_runtime.h>
#include <cuda_bf16.h>
#include <cstdint>
#include <cstddef>

// Problem constants
#define B_  32
#define S_  2048
#define F_  512
#define MOMENTUM 0.1f
#define EPS 1e-5f

// ---------------- device scratch (static, no allocations) ----------------
__device__ float g_xn   [(size_t)B_ * S_ * F_];   // 128 MB  centered input
__device__ float g_sigma[(size_t)B_ * F_ * F_];
__device__ float g_P    [(size_t)B_ * F_ * F_];
__device__ float g_Q    [(size_t)B_ * F_ * F_];
__device__ float g_T1   [(size_t)B_ * F_ * F_];
__device__ float g_T2   [(size_t)B_ * F_ * F_];
__device__ float g_meanp[16 * B_ * F_];           // partial sums [b][sc][f]
__device__ float g_mean [B_ * F_];
__device__ float g_invtr[B_];
__device__ float g_rstr [B_];

// ---------------- elementwise kernels ----------------
// phase 1: partial sums over 128-row chunks (full-chip parallel)
__global__ void mean_p1_kernel(const float* __restrict__ x,
                               float* __restrict__ meanp) {
    int sc = blockIdx.x;           // 0..15
    int b  = blockIdx.y;
    int f  = threadIdx.x;
    const float* xb = x + (size_t)b * S_ * F_ + (size_t)sc * 128 * F_ + f;
    float acc = 0.f;
    #pragma unroll 8
    for (int s = 0; s < 128; s++) acc += xb[(size_t)s * F_];
    meanp[((size_t)b * 16 + sc) * F_ + f] = acc;
}

// phase 2: reduce 16 partials + blend with running mean
__global__ void mean_p2_kernel(const float* __restrict__ meanp,
                               const float* __restrict__ rm,
                               float* __restrict__ mean) {
    int b = blockIdx.x;
    int f = threadIdx.x;
    const float* mp = meanp + (size_t)b * 16 * F_ + f;
    float acc = 0.f;
    #pragma unroll
    for (int i = 0; i < 16; i++) acc += mp[(size_t)i * F_];
    mean[b * F_ + f] = (1.f - MOMENTUM) * rm[f] + MOMENTUM * (acc * (1.f / (float)S_));
}

__global__ void xn_kernel(const float* __restrict__ x,
                          const float* __restrict__ mean,
                          float* __restrict__ xn) {
    size_t p4 = (size_t)blockIdx.x * blockDim.x + threadIdx.x;
    size_t p  = p4 * 4;
    int b = (int)(p >> 20);            // S*F = 2^20
    int f = (int)(p & (F_ - 1));
    float4 xv = *(const float4*)(x + p);
    float4 mv = *(const float4*)(mean + b * F_ + f);
    float4 o;
    o.x = xv.x - mv.x; o.y = xv.y - mv.y; o.z = xv.z - mv.z; o.w = xv.w - mv.w;
    *(float4*)(xn + p) = o;
}

__global__ void trace_kernel(const float* __restrict__ sigma,
                             float* __restrict__ invtr,
                             float* __restrict__ rstr) {
    __shared__ float red[512];
    int b = blockIdx.x, t = threadIdx.x;
    red[t] = sigma[(size_t)b * F_ * F_ + (size_t)t * (F_ + 1)];
    __syncthreads();
    for (int s = 256; s > 0; s >>= 1) {
        if (t < s) red[t] += red[t + s];
        __syncthreads();
    }
    if (t == 0) {
        float tr = red[0];
        invtr[b] = 1.f / tr;
        rstr[b]  = 1.f / sqrtf(tr);
    }
}

__global__ void initp_kernel(const float* __restrict__ sigma,
                             const float* __restrict__ invtr,
                             float* __restrict__ P) {
    size_t idx = (size_t)blockIdx.x * blockDim.x + threadIdx.x;
    int b = (int)(idx >> 18);
    int r = (int)((idx >> 9) & (F_ - 1));
    int c = (int)(idx & (F_ - 1));
    float v = -0.5f * invtr[b] * sigma[idx];
    if (r == c) v += 1.5f;
    P[idx] = v;
}

// ---------------- helpers ----------------
__device__ __forceinline__ void cp_async16(void* smem_dst, const void* gmem_src) {
    uint32_t s = (uint32_t)__cvta_generic_to_shared(smem_dst);
    asm volatile("cp.async.cg.shared.global [%0], [%1], 16;\n" :: "r"(s), "l"(gmem_src));
}
#define CP_COMMIT asm volatile("cp.async.commit_group;" ::: "memory")
#define CP_WAIT0  asm volatile("cp.async.wait_group 0;"  ::: "memory")

// split fp32 pair into packed bf16 hi / bf16 lo (x -> lower 16 bits).
// hi via packed cvt (RN); residuals from unpacked hi; lo via packed cvt.
__device__ __forceinline__ void split2_bf16(float x, float y, uint32_t& h, uint32_t& l) {
    uint32_t hp;
    asm("cvt.rn.bf16x2.f32 %0, %1, %2;" : "=r"(hp) : "f"(y), "f"(x));   // y->hi, x->lo
    float hx = __uint_as_float(hp << 16);
    float hy = __uint_as_float(hp & 0xFFFF0000u);
    float lx = x - hx;
    float ly = y - hy;
    uint32_t lp;
    asm("cvt.rn.bf16x2.f32 %0, %1, %2;" : "=r"(lp) : "f"(ly), "f"(lx));
    h = hp;
    l = lp;
}

__device__ __forceinline__ void mma_bf16(float* c, const uint32_t* a, const uint32_t* b) {
    asm volatile(
        "mma.sync.aligned.m16n8k16.row.col.f32.bf16.bf16.f32 "
        "{%0,%1,%2,%3}, {%4,%5,%6,%7}, {%8,%9}, {%0,%1,%2,%3};"
        : "+f"(c[0]), "+f"(c[1]), "+f"(c[2]), "+f"(c[3])
        : "r"(a[0]), "r"(a[1]), "r"(a[2]), "r"(a[3]), "r"(b[0]), "r"(b[1]));
}

__device__ __forceinline__ void ldsm_x4(uint32_t& r0, uint32_t& r1, uint32_t& r2,
                                        uint32_t& r3, uint32_t addr) {
    asm volatile("ldmatrix.sync.aligned.m8n8.x4.shared.b16 {%0,%1,%2,%3}, [%4];"
                 : "=r"(r0), "=r"(r1), "=r"(r2), "=r"(r3) : "r"(addr));
}
__device__ __forceinline__ void ldsm_x2(uint32_t& r0, uint32_t& r1, uint32_t addr) {
    asm volatile("ldmatrix.sync.aligned.m8n8.x2.shared.b16 {%0,%1}, [%2];"
                 : "=r"(r0), "=r"(r1) : "r"(addr));
}

// ---------------- bf16x3 tensor-core GEMM ----------------
// R15 structure (single fp32 stage + convert + single bf16 stage, 76KB,
// 2 CTAs/SM, ldmatrix mainloop, PAIR variant) with cheaper packed-cvt split
// and term-major MMA ordering.
// mode 0: C = AB
// mode 1: C = 1.5*D - 0.5*scale[b]*AB
// mode 2: C = scale[b]*AB
// mode 3: C = 0.9*E + 0.1*(AB/(S-1) + eps*I)   (E has no batch stride)
#define STG_FP32_B 36864
#define OFF_BF     STG_FP32_B                 // 36864
#define BF_STAGE_B 40960
#define GEMM_SMEM_TOTAL (OFF_BF + BF_STAGE_B) // 77824

template<int TRANSA, int TRI, int PAIR>
__global__ __launch_bounds__(256, 2) void gemm_bf16x3_kernel(
        const float* __restrict__ Ag, const float* __restrict__ Bg,
        float* __restrict__ Cg, const float* __restrict__ Dg,
        const float* __restrict__ Eg, const float* __restrict__ scale,
        int M, int N, int K, int mode,
        size_t sAb, size_t sBb, size_t sCb,
        const float* __restrict__ Ag2, const float* __restrict__ Bg2,
        float* __restrict__ Cg2) {
    extern __shared__ char smem[];

    int bz = blockIdx.z;
    int t = blockIdx.x;
    const float* Asel = Ag;
    const float* Bsel = Bg;
    float* Csel = Cg;
    if (PAIR && t >= 10) {
        t -= 10;
        Asel = Ag2; Bsel = Bg2; Csel = Cg2;
    }
    const float* A = Asel + (size_t)bz * sAb;
    const float* Bm = Bsel + (size_t)bz * sBb;
    float* C = Csel + (size_t)bz * sCb;

    int m0, n0;
    bool mirror = false;
    if (TRI) {
        int bi = (t < 4) ? 0 : (t < 7) ? 1 : (t < 9) ? 2 : 3;
        int start = (bi == 0) ? 0 : (bi == 1) ? 4 : (bi == 2) ? 7 : 9;
        int bj = bi + (t - start);
        m0 = bi * 128; n0 = bj * 128;
        mirror = (bi != bj);
    } else {
        m0 = blockIdx.y * 128;
        n0 = blockIdx.x * 128;
    }

    int tid  = threadIdx.x;
    int lane = tid & 31;
    int wid  = tid >> 5;
    int warp_m = (wid >> 2) * 64;     // 0 or 64
    int warp_n = (wid & 3) * 32;      // 0,32,64,96
    int g  = lane >> 2;               // 0..7
    int tg = lane & 3;                // 0..3

    float acc[4][4][4];
    #pragma unroll
    for (int i = 0; i < 4; i++)
        #pragma unroll
        for (int j = 0; j < 4; j++)
            #pragma unroll
            for (int q = 0; q < 4; q++) acc[i][j][q] = 0.f;

    // ---- cp.async staging of fp32 tiles (single stage) ----
    auto prefetch = [&](int k0) {
        float* sA = (float*)smem;
        float* sB = sA + 4608;
        if (!TRANSA) {
            #pragma unroll
            for (int p = 0; p < 4; p++) {
                int c = tid + p * 256;
                int m = c >> 3;
                int kc = (c & 7) * 4;
                cp_async16(sA + m * 36 + kc, A + (size_t)(m0 + m) * K + k0 + kc);
            }
        } else {
            #pragma unroll
            for (int p = 0; p < 4; p++) {
                int c = tid + p * 256;
                int k = c >> 5;
                int mc = (c & 31) * 4;
                cp_async16(sA + k * 132 + mc, A + (size_t)(k0 + k) * M + m0 + mc);
            }
        }
        #pragma unroll
        for (int p = 0; p < 4; p++) {
            int c = tid + p * 256;
            int k = c >> 5;
            int nc = (c & 31) * 4;
            cp_async16(sB + k * 132 + nc, Bm + (size_t)(k0 + k) * N + n0 + nc);
        }
    };

    prefetch(0);
    CP_COMMIT;

    const int NC = K >> 5;
    const int mrow = tid >> 1;             // 0..127
    const int ks   = (tid & 1) * 16;       // 0 or 16

    // ldmatrix lane base addresses (bytes, shared space)
    uint32_t sbf = (uint32_t)__cvta_generic_to_shared(smem + OFF_BF);
    uint32_t aoff = sbf + (uint32_t)(((warp_m + (lane & 15)) * 40 + (lane >> 4) * 8) * 2);
    uint32_t boff = sbf + 20480u + (uint32_t)(((warp_n + (lane & 7)) * 40 + ((lane >> 3) & 1) * 8) * 2);

    for (int c = 0; c < NC; c++) {
        CP_WAIT0;
        __syncthreads();   // fp32 stage ready; previous mainloop done

        // ---- convert: fp32 stage -> packed bf16 hi/lo (B transposed) ----
        {
            const float* fA = (const float*)smem;
            const float* fB = fA + 4608;
            char* bf = smem + OFF_BF;
            uint32_t* dAh = (uint32_t*)(bf +      0 + (size_t)(mrow * 40 + ks) * 2);
            uint32_t* dAl = (uint32_t*)(bf +  10240 + (size_t)(mrow * 40 + ks) * 2);
            uint32_t* dBh = (uint32_t*)(bf +  20480 + (size_t)(mrow * 40 + ks) * 2);
            uint32_t* dBl = (uint32_t*)(bf +  30720 + (size_t)(mrow * 40 + ks) * 2);
            if (!TRANSA) {
                const float* s = fA + mrow * 36 + ks;
                #pragma unroll
                for (int u = 0; u < 4; u++) {
                    float4 v = *(const float4*)(s + 4 * u);
                    uint32_t h0, l0, h1, l1;
                    split2_bf16(v.x, v.y, h0, l0);
                    split2_bf16(v.z, v.w, h1, l1);
                    dAh[2 * u] = h0; dAh[2 * u + 1] = h1;
                    dAl[2 * u] = l0; dAl[2 * u + 1] = l1;
                }
            } else {
                const float* s = fA + mrow;      // [k][132]
                #pragma unroll
                for (int u = 0; u < 8; u++) {
                    float v0 = s[(ks + 2 * u) * 132];
                    float v1 = s[(ks + 2 * u + 1) * 132];
                    uint32_t h, l;
                    split2_bf16(v0, v1, h, l);
                    dAh[u] = h; dAl[u] = l;
                }
            }
            const float* s = fB + mrow;          // [k][132], col = mrow (transpose)
            #pragma unroll
            for (int u = 0; u < 8; u++) {
                float v0 = s[(ks + 2 * u) * 132];
                float v1 = s[(ks + 2 * u + 1) * 132];
                uint32_t h, l;
                split2_bf16(v0, v1, h, l);
                dBh[u] = h; dBl[u] = l;
            }
        }
        __syncthreads();   // all convert reads of fp32 stage complete

        // issue next chunk's copies; they overlap the mainloop below
        if (c + 1 < NC) {
            prefetch((c + 1) * 32);
            CP_COMMIT;
        }

        // ---- mainloop: ldmatrix fragment loads + HMMA (term-major) ----
        #pragma unroll
        for (int kk = 0; kk < 32; kk += 16) {
            uint32_t kb = (uint32_t)(kk * 2);
            uint32_t bh[4][2], bl[4][2];
            #pragma unroll
            for (int j = 0; j < 4; j++) {
                uint32_t ba = boff + (uint32_t)(j * 640) + kb;
                ldsm_x2(bh[j][0], bh[j][1], ba);
                ldsm_x2(bl[j][0], bl[j][1], ba + 10240u);
            }
            #pragma unroll
            for (int i = 0; i < 4; i++) {
                uint32_t aa = aoff + (uint32_t)(i * 1280) + kb;
                uint32_t ah[4], al[4];
                ldsm_x4(ah[0], ah[1], ah[2], ah[3], aa);
                ldsm_x4(al[0], al[1], al[2], al[3], aa + 10240u);
                #pragma unroll
                for (int j = 0; j < 4; j++) mma_bf16(acc[i][j], ah, bh[j]);  // hi*hi
                #pragma unroll
                for (int j = 0; j < 4; j++) mma_bf16(acc[i][j], ah, bl[j]);  // hi*lo
                #pragma unroll
                for (int j = 0; j < 4; j++) mma_bf16(acc[i][j], al, bh[j]);  // lo*hi
            }
        }
    }

    // ---- epilogue ----
    float sc = 0.f;
    if (mode == 1) sc = -0.5f * scale[bz];
    else if (mode == 2) sc = scale[bz];
    const float* D = (mode == 1) ? (Dg + (size_t)bz * sCb) : nullptr;
    const float inv_nm1 = 1.f / (float)(S_ - 1);

    #pragma unroll
    for (int i = 0; i < 4; i++) {
        #pragma unroll
        for (int j = 0; j < 4; j++) {
            int r0 = m0 + warp_m + i * 16 + g;
            int c0 = n0 + warp_n + j * 8 + 2 * tg;
            #pragma unroll
            for (int half = 0; half < 2; half++) {
                int r = r0 + half * 8;
                float v0 = acc[i][j][half * 2 + 0];
                float v1 = acc[i][j][half * 2 + 1];
                size_t off = (size_t)r * N + c0;
                float2 o;
                if (mode == 0 || (PAIR && blockIdx.x >= 10)) {
                    o.x = v0; o.y = v1;
                } else if (mode == 1) {
                    o.x = 1.5f * D[off] + sc * v0;
                    o.y = 1.5f * D[off + 1] + sc * v1;
                } else if (mode == 2) {
                    o.x = sc * v0; o.y = sc * v1;
                } else {
                    float s0 = v0 * inv_nm1 + ((r == c0)     ? EPS : 0.f);
                    float s1 = v1 * inv_nm1 + ((r == c0 + 1) ? EPS : 0.f);
                    o.x = (1.f - MOMENTUM) * Eg[off] + MOMENTUM * s0;
                    o.y = (1.f - MOMENTUM) * Eg[off + 1] + MOMENTUM * s1;
                }
                *(float2*)(C + off) = o;
                if (TRI && mirror) {
                    C[(size_t)c0 * N + r]       = o.x;
                    C[(size_t)(c0 + 1) * N + r] = o.y;
                }
            }
        }
    }
}

// ---------------- host launcher ----------------
extern "C" void kernel_launch(void* const* d_in, const int* in_sizes, int n_in,
                              void* d_out, int out_size) {
    const float* x  = (const float*)d_in[0];
    const float* rm = (const float*)d_in[1];
    const float* rc = (const float*)d_in[2];
    float* out = (float*)d_out;

    float *xn, *sigma, *P, *Q, *T1, *T2, *meanp, *mean, *invtr, *rstr;
    cudaGetSymbolAddress((void**)&xn,    g_xn);
    cudaGetSymbolAddress((void**)&sigma, g_sigma);
    cudaGetSymbolAddress((void**)&P,     g_P);
    cudaGetSymbolAddress((void**)&Q,     g_Q);
    cudaGetSymbolAddress((void**)&T1,    g_T1);
    cudaGetSymbolAddress((void**)&T2,    g_T2);
    cudaGetSymbolAddress((void**)&meanp, g_meanp);
    cudaGetSymbolAddress((void**)&mean,  g_mean);
    cudaGetSymbolAddress((void**)&invtr, g_invtr);
    cudaGetSymbolAddress((void**)&rstr,  g_rstr);

    static bool attr_set = false;
    if (!attr_set) {
        cudaFuncSetAttribute(gemm_bf16x3_kernel<0,0,0>,
            cudaFuncAttributeMaxDynamicSharedMemorySize, GEMM_SMEM_TOTAL);
        cudaFuncSetAttribute(gemm_bf16x3_kernel<0,1,0>,
            cudaFuncAttributeMaxDynamicSharedMemorySize, GEMM_SMEM_TOTAL);
        cudaFuncSetAttribute(gemm_bf16x3_kernel<1,1,0>,
            cudaFuncAttributeMaxDynamicSharedMemorySize, GEMM_SMEM_TOTAL);
        cudaFuncSetAttribute(gemm_bf16x3_kernel<0,1,1>,
            cudaFuncAttributeMaxDynamicSharedMemorySize, GEMM_SMEM_TOTAL);
        attr_set = true;
    }

    const size_t FF = (size_t)F_ * F_;
    const size_t SF = (size_t)S_ * F_;

    // 1. blended mean (two-phase, full-chip parallel)
    mean_p1_kernel<<<dim3(16, B_), F_>>>(x, meanp);
    mean_p2_kernel<<<B_, F_>>>(meanp, rm, mean);
    // 2. xn = x - m
    xn_kernel<<<(unsigned)((size_t)B_ * SF / 4 / 256), 256>>>(x, mean, xn);
    // 3. sigma = 0.9*rc + 0.1*(xn^T xn /(S-1) + eps*I)  [transA SYRK, triangular]
    gemm_bf16x3_kernel<1,1,0><<<dim3(10, 1, B_), 256, GEMM_SMEM_TOTAL>>>(
        xn, xn, sigma, nullptr, rc, nullptr, F_, F_, S_, 3, SF, SF, FF,
        nullptr, nullptr, nullptr);
    // 4. trace
    trace_kernel<<<B_, F_>>>(sigma, invtr, rstr);
    // 5. P1 = 1.5I - 0.5 sigma/tr
    initp_kernel<<<(unsigned)((size_t)B_ * FF / 256), 256>>>(sigma, invtr, P);

    // 6. NS iterations 2..4:  P' = 1.5P - 0.5/tr * (P^2)*(P sigma)
    //    T1 = P*P and T2 = P*sigma are independent -> one paired launch.
    float* Pin = P;
    float* Pout = Q;
    for (int it = 0; it < 3; it++) {
        gemm_bf16x3_kernel<0,1,1><<<dim3(20, 1, B_), 256, GEMM_SMEM_TOTAL>>>(
            Pin, Pin, T1, nullptr, nullptr, nullptr, F_, F_, F_, 0, FF, FF, FF,
            Pin, sigma, T2);
        gemm_bf16x3_kernel<0,1,0><<<dim3(10, 1, B_), 256, GEMM_SMEM_TOTAL>>>(
            T1, T2, Pout, Pin, nullptr, invtr, F_, F_, F_, 1, FF, FF, FF,
            nullptr, nullptr, nullptr);
        float* tmp = Pin; Pin = Pout; Pout = tmp;
    }

    // 7. out = (xn @ P) * rsqrt(tr)
    gemm_bf16x3_kernel<0,0,0><<<dim3(4, 16, B_), 256, GEMM_SMEM_TOTAL>>>(
        xn, Pin, out, nullptr, nullptr, rstr, S_, F_, F_, 2, SF, FF, SF,
        nullptr, nullptr, nullptr);
}

// round 17
// speedup vs baseline: 1.2872x; 1.0390x over previous
#include <cuda_runtime.h>
#include <cuda_bf16.h>
#include <cstdint>
#include <cstddef>

// Problem constants
#define B_  32
#define S_  2048
#define F_  512
#define MOMENTUM 0.1f
#define EPS 1e-5f

// ---------------- device scratch (static, no allocations) ----------------
__device__ float g_xn   [(size_t)B_ * S_ * F_];   // 128 MB  centered input
__device__ float g_part [(size_t)4 * B_ * F_ * F_]; // 128 MB SYRK K-partials
__device__ float g_sigma[(size_t)B_ * F_ * F_];
__device__ float g_P    [(size_t)B_ * F_ * F_];
__device__ float g_Q    [(size_t)B_ * F_ * F_];
__device__ float g_T1   [(size_t)B_ * F_ * F_];
__device__ float g_T2   [(size_t)B_ * F_ * F_];
__device__ float g_meanp[16 * B_ * F_];           // partial sums [b][sc][f]
__device__ float g_mean [B_ * F_];
__device__ float g_invtr[B_];
__device__ float g_rstr [B_];

// ---------------- elementwise kernels ----------------
__global__ void mean_p1_kernel(const float* __restrict__ x,
                               float* __restrict__ meanp) {
    int sc = blockIdx.x;           // 0..15
    int b  = blockIdx.y;
    int f  = threadIdx.x;
    const float* xb = x + (size_t)b * S_ * F_ + (size_t)sc * 128 * F_ + f;
    float acc = 0.f;
    #pragma unroll 8
    for (int s = 0; s < 128; s++) acc += xb[(size_t)s * F_];
    meanp[((size_t)b * 16 + sc) * F_ + f] = acc;
}

__global__ void mean_p2_kernel(const float* __restrict__ meanp,
                               const float* __restrict__ rm,
                               float* __restrict__ mean) {
    int b = blockIdx.x;
    int f = threadIdx.x;
    const float* mp = meanp + (size_t)b * 16 * F_ + f;
    float acc = 0.f;
    #pragma unroll
    for (int i = 0; i < 16; i++) acc += mp[(size_t)i * F_];
    mean[b * F_ + f] = (1.f - MOMENTUM) * rm[f] + MOMENTUM * (acc * (1.f / (float)S_));
}

__global__ void xn_kernel(const float* __restrict__ x,
                          const float* __restrict__ mean,
                          float* __restrict__ xn) {
    size_t p4 = (size_t)blockIdx.x * blockDim.x + threadIdx.x;
    size_t p  = p4 * 4;
    int b = (int)(p >> 20);            // S*F = 2^20
    int f = (int)(p & (F_ - 1));
    float4 xv = *(const float4*)(x + p);
    float4 mv = *(const float4*)(mean + b * F_ + f);
    float4 o;
    o.x = xv.x - mv.x; o.y = xv.y - mv.y; o.z = xv.z - mv.z; o.w = xv.w - mv.w;
    *(float4*)(xn + p) = o;
}

// sum 4 SYRK K-partials, blend with running covariance, add eps*I
__global__ void reduce_sigma_kernel(const float* __restrict__ part,
                                    const float* __restrict__ rc,
                                    float* __restrict__ sigma) {
    size_t p4 = (size_t)blockIdx.x * blockDim.x + threadIdx.x;
    size_t idx = p4 * 4;
    int r = (int)((idx >> 9) & (F_ - 1));
    int c = (int)(idx & (F_ - 1));
    size_t fo = idx & ((size_t)F_ * F_ - 1);   // offset within one matrix (rc index)
    const size_t stride = (size_t)B_ * F_ * F_;
    float4 s0 = *(const float4*)(part + idx);
    float4 s1 = *(const float4*)(part + stride + idx);
    float4 s2 = *(const float4*)(part + 2 * stride + idx);
    float4 s3 = *(const float4*)(part + 3 * stride + idx);
    float4 rcv = *(const float4*)(rc + fo);
    const float inv_nm1 = 1.f / (float)(S_ - 1);
    float4 o;
    o.x = (1.f - MOMENTUM) * rcv.x + MOMENTUM * ((s0.x + s1.x + s2.x + s3.x) * inv_nm1 + ((r == c)     ? EPS : 0.f));
    o.y = (1.f - MOMENTUM) * rcv.y + MOMENTUM * ((s0.y + s1.y + s2.y + s3.y) * inv_nm1 + ((r == c + 1) ? EPS : 0.f));
    o.z = (1.f - MOMENTUM) * rcv.z + MOMENTUM * ((s0.z + s1.z + s2.z + s3.z) * inv_nm1 + ((r == c + 2) ? EPS : 0.f));
    o.w = (1.f - MOMENTUM) * rcv.w + MOMENTUM * ((s0.w + s1.w + s2.w + s3.w) * inv_nm1 + ((r == c + 3) ? EPS : 0.f));
    *(float4*)(sigma + idx) = o;
}

__global__ void trace_kernel(const float* __restrict__ sigma,
                             float* __restrict__ invtr,
                             float* __restrict__ rstr) {
    __shared__ float red[512];
    int b = blockIdx.x, t = threadIdx.x;
    red[t] = sigma[(size_t)b * F_ * F_ + (size_t)t * (F_ + 1)];
    __syncthreads();
    for (int s = 256; s > 0; s >>= 1) {
        if (t < s) red[t] += red[t + s];
        __syncthreads();
    }
    if (t == 0) {
        float tr = red[0];
        invtr[b] = 1.f / tr;
        rstr[b]  = 1.f / sqrtf(tr);
    }
}

__global__ void initp_kernel(const float* __restrict__ sigma,
                             const float* __restrict__ invtr,
                             float* __restrict__ P) {
    size_t idx = (size_t)blockIdx.x * blockDim.x + threadIdx.x;
    int b = (int)(idx >> 18);
    int r = (int)((idx >> 9) & (F_ - 1));
    int c = (int)(idx & (F_ - 1));
    float v = -0.5f * invtr[b] * sigma[idx];
    if (r == c) v += 1.5f;
    P[idx] = v;
}

// ---------------- helpers ----------------
__device__ __forceinline__ void cp_async16(void* smem_dst, const void* gmem_src) {
    uint32_t s = (uint32_t)__cvta_generic_to_shared(smem_dst);
    asm volatile("cp.async.cg.shared.global [%0], [%1], 16;\n" :: "r"(s), "l"(gmem_src));
}
#define CP_COMMIT asm volatile("cp.async.commit_group;" ::: "memory")
#define CP_WAIT0  asm volatile("cp.async.wait_group 0;"  ::: "memory")

// split fp32 pair into packed bf16 hi / bf16 lo (x -> lower 16 bits)
__device__ __forceinline__ void split2_bf16(float x, float y, uint32_t& h, uint32_t& l) {
    uint32_t hp;
    asm("cvt.rn.bf16x2.f32 %0, %1, %2;" : "=r"(hp) : "f"(y), "f"(x));   // y->hi, x->lo
    float hx = __uint_as_float(hp << 16);
    float hy = __uint_as_float(hp & 0xFFFF0000u);
    float lx = x - hx;
    float ly = y - hy;
    uint32_t lp;
    asm("cvt.rn.bf16x2.f32 %0, %1, %2;" : "=r"(lp) : "f"(ly), "f"(lx));
    h = hp;
    l = lp;
}

__device__ __forceinline__ void mma_bf16(float* c, const uint32_t* a, const uint32_t* b) {
    asm volatile(
        "mma.sync.aligned.m16n8k16.row.col.f32.bf16.bf16.f32 "
        "{%0,%1,%2,%3}, {%4,%5,%6,%7}, {%8,%9}, {%0,%1,%2,%3};"
        : "+f"(c[0]), "+f"(c[1]), "+f"(c[2]), "+f"(c[3])
        : "r"(a[0]), "r"(a[1]), "r"(a[2]), "r"(a[3]), "r"(b[0]), "r"(b[1]));
}

__device__ __forceinline__ void ldsm_x4(uint32_t& r0, uint32_t& r1, uint32_t& r2,
                                        uint32_t& r3, uint32_t addr) {
    asm volatile("ldmatrix.sync.aligned.m8n8.x4.shared.b16 {%0,%1,%2,%3}, [%4];"
                 : "=r"(r0), "=r"(r1), "=r"(r2), "=r"(r3) : "r"(addr));
}
__device__ __forceinline__ void ldsm_x2(uint32_t& r0, uint32_t& r1, uint32_t addr) {
    asm volatile("ldmatrix.sync.aligned.m8n8.x2.shared.b16 {%0,%1}, [%2];"
                 : "=r"(r0), "=r"(r1) : "r"(addr));
}

// ---------------- bf16x3 tensor-core GEMM ----------------
// R16 structure. New KSPLIT template: blockIdx.y selects a 512-row K-slab of
// both operands and redirects C to per-quarter partial buffers (Cg must point
// at g_part; layout [q][b][F][F]).
// mode 0: C = AB
// mode 1: C = 1.5*D - 0.5*scale[b]*AB
// mode 2: C = scale[b]*AB
// mode 3: C = 0.9*E + 0.1*(AB/(S-1) + eps*I)   (E has no batch stride)
#define STG_FP32_B 36864
#define OFF_BF     STG_FP32_B                 // 36864
#define BF_STAGE_B 40960
#define GEMM_SMEM_TOTAL (OFF_BF + BF_STAGE_B) // 77824

template<int TRANSA, int TRI, int PAIR, int KSPLIT>
__global__ __launch_bounds__(256, 2) void gemm_bf16x3_kernel(
        const float* __restrict__ Ag, const float* __restrict__ Bg,
        float* __restrict__ Cg, const float* __restrict__ Dg,
        const float* __restrict__ Eg, const float* __restrict__ scale,
        int M, int N, int K, int mode,
        size_t sAb, size_t sBb, size_t sCb,
        const float* __restrict__ Ag2, const float* __restrict__ Bg2,
        float* __restrict__ Cg2) {
    extern __shared__ char smem[];

    int bz = blockIdx.z;
    int t = blockIdx.x;
    const float* Asel = Ag;
    const float* Bsel = Bg;
    float* Csel = Cg;
    if (PAIR && t >= 10) {
        t -= 10;
        Asel = Ag2; Bsel = Bg2; Csel = Cg2;
    }
    const float* A = Asel + (size_t)bz * sAb;
    const float* Bm = Bsel + (size_t)bz * sBb;
    float* C = Csel + (size_t)bz * sCb;
    if (KSPLIT) {
        int q = blockIdx.y;
        A  += (size_t)q * K * M;    // k-major slab advance (TRANSA layout)
        Bm += (size_t)q * K * N;
        C = Csel + ((size_t)q * gridDim.z + bz) * sCb;
    }

    int m0, n0;
    bool mirror = false;
    if (TRI) {
        int bi = (t < 4) ? 0 : (t < 7) ? 1 : (t < 9) ? 2 : 3;
        int start = (bi == 0) ? 0 : (bi == 1) ? 4 : (bi == 2) ? 7 : 9;
        int bj = bi + (t - start);
        m0 = bi * 128; n0 = bj * 128;
        mirror = (bi != bj);
    } else {
        m0 = blockIdx.y * 128;
        n0 = blockIdx.x * 128;
    }

    int tid  = threadIdx.x;
    int lane = tid & 31;
    int wid  = tid >> 5;
    int warp_m = (wid >> 2) * 64;     // 0 or 64
    int warp_n = (wid & 3) * 32;      // 0,32,64,96
    int g  = lane >> 2;               // 0..7
    int tg = lane & 3;                // 0..3

    float acc[4][4][4];
    #pragma unroll
    for (int i = 0; i < 4; i++)
        #pragma unroll
        for (int j = 0; j < 4; j++)
            #pragma unroll
            for (int q = 0; q < 4; q++) acc[i][j][q] = 0.f;

    // ---- cp.async staging of fp32 tiles (single stage) ----
    auto prefetch = [&](int k0) {
        float* sA = (float*)smem;
        float* sB = sA + 4608;
        if (!TRANSA) {
            #pragma unroll
            for (int p = 0; p < 4; p++) {
                int c = tid + p * 256;
                int m = c >> 3;
                int kc = (c & 7) * 4;
                cp_async16(sA + m * 36 + kc, A + (size_t)(m0 + m) * K + k0 + kc);
            }
        } else {
            #pragma unroll
            for (int p = 0; p < 4; p++) {
                int c = tid + p * 256;
                int k = c >> 5;
                int mc = (c & 31) * 4;
                cp_async16(sA + k * 132 + mc, A + (size_t)(k0 + k) * M + m0 + mc);
            }
        }
        #pragma unroll
        for (int p = 0; p < 4; p++) {
            int c = tid + p * 256;
            int k = c >> 5;
            int nc = (c & 31) * 4;
            cp_async16(sB + k * 132 + nc, Bm + (size_t)(k0 + k) * N + n0 + nc);
        }
    };

    prefetch(0);
    CP_COMMIT;

    const int NC = K >> 5;
    const int mrow = tid >> 1;             // 0..127
    const int ks   = (tid & 1) * 16;       // 0 or 16

    // ldmatrix lane base addresses (bytes, shared space)
    uint32_t sbf = (uint32_t)__cvta_generic_to_shared(smem + OFF_BF);
    uint32_t aoff = sbf + (uint32_t)(((warp_m + (lane & 15)) * 40 + (lane >> 4) * 8) * 2);
    uint32_t boff = sbf + 20480u + (uint32_t)(((warp_n + (lane & 7)) * 40 + ((lane >> 3) & 1) * 8) * 2);

    for (int c = 0; c < NC; c++) {
        CP_WAIT0;
        __syncthreads();   // fp32 stage ready; previous mainloop done

        // ---- convert: fp32 stage -> packed bf16 hi/lo (B transposed) ----
        {
            const float* fA = (const float*)smem;
            const float* fB = fA + 4608;
            char* bf = smem + OFF_BF;
            uint32_t* dAh = (uint32_t*)(bf +      0 + (size_t)(mrow * 40 + ks) * 2);
            uint32_t* dAl = (uint32_t*)(bf +  10240 + (size_t)(mrow * 40 + ks) * 2);
            uint32_t* dBh = (uint32_t*)(bf +  20480 + (size_t)(mrow * 40 + ks) * 2);
            uint32_t* dBl = (uint32_t*)(bf +  30720 + (size_t)(mrow * 40 + ks) * 2);
            if (!TRANSA) {
                const float* s = fA + mrow * 36 + ks;
                #pragma unroll
                for (int u = 0; u < 4; u++) {
                    float4 v = *(const float4*)(s + 4 * u);
                    uint32_t h0, l0, h1, l1;
                    split2_bf16(v.x, v.y, h0, l0);
                    split2_bf16(v.z, v.w, h1, l1);
                    dAh[2 * u] = h0; dAh[2 * u + 1] = h1;
                    dAl[2 * u] = l0; dAl[2 * u + 1] = l1;
                }
            } else {
                const float* s = fA + mrow;      // [k][132]
                #pragma unroll
                for (int u = 0; u < 8; u++) {
                    float v0 = s[(ks + 2 * u) * 132];
                    float v1 = s[(ks + 2 * u + 1) * 132];
                    uint32_t h, l;
                    split2_bf16(v0, v1, h, l);
                    dAh[u] = h; dAl[u] = l;
                }
            }
            const float* s = fB + mrow;          // [k][132], col = mrow (transpose)
            #pragma unroll
            for (int u = 0; u < 8; u++) {
                float v0 = s[(ks + 2 * u) * 132];
                float v1 = s[(ks + 2 * u + 1) * 132];
                uint32_t h, l;
                split2_bf16(v0, v1, h, l);
                dBh[u] = h; dBl[u] = l;
            }
        }
        __syncthreads();   // all convert reads of fp32 stage complete

        // issue next chunk's copies; they overlap the mainloop below
        if (c + 1 < NC) {
            prefetch((c + 1) * 32);
            CP_COMMIT;
        }

        // ---- mainloop: ldmatrix fragment loads + HMMA (term-major) ----
        #pragma unroll
        for (int kk = 0; kk < 32; kk += 16) {
            uint32_t kb = (uint32_t)(kk * 2);
            uint32_t bh[4][2], bl[4][2];
            #pragma unroll
            for (int j = 0; j < 4; j++) {
                uint32_t ba = boff + (uint32_t)(j * 640) + kb;
                ldsm_x2(bh[j][0], bh[j][1], ba);
                ldsm_x2(bl[j][0], bl[j][1], ba + 10240u);
            }
            #pragma unroll
            for (int i = 0; i < 4; i++) {
                uint32_t aa = aoff + (uint32_t)(i * 1280) + kb;
                uint32_t ah[4], al[4];
                ldsm_x4(ah[0], ah[1], ah[2], ah[3], aa);
                ldsm_x4(al[0], al[1], al[2], al[3], aa + 10240u);
                #pragma unroll
                for (int j = 0; j < 4; j++) mma_bf16(acc[i][j], ah, bh[j]);  // hi*hi
                #pragma unroll
                for (int j = 0; j < 4; j++) mma_bf16(acc[i][j], ah, bl[j]);  // hi*lo
                #pragma unroll
                for (int j = 0; j < 4; j++) mma_bf16(acc[i][j], al, bh[j]);  // lo*hi
            }
        }
    }

    // ---- epilogue ----
    float sc = 0.f;
    if (mode == 1) sc = -0.5f * scale[bz];
    else if (mode == 2) sc = scale[bz];
    const float* D = (mode == 1) ? (Dg + (size_t)bz * sCb) : nullptr;
    const float inv_nm1 = 1.f / (float)(S_ - 1);

    #pragma unroll
    for (int i = 0; i < 4; i++) {
        #pragma unroll
        for (int j = 0; j < 4; j++) {
            int r0 = m0 + warp_m + i * 16 + g;
            int c0 = n0 + warp_n + j * 8 + 2 * tg;
            #pragma unroll
            for (int half = 0; half < 2; half++) {
                int r = r0 + half * 8;
                float v0 = acc[i][j][half * 2 + 0];
                float v1 = acc[i][j][half * 2 + 1];
                size_t off = (size_t)r * N + c0;
                float2 o;
                if (mode == 0 || (PAIR && blockIdx.x >= 10)) {
                    o.x = v0; o.y = v1;
                } else if (mode == 1) {
                    o.x = 1.5f * D[off] + sc * v0;
                    o.y = 1.5f * D[off + 1] + sc * v1;
                } else if (mode == 2) {
                    o.x = sc * v0; o.y = sc * v1;
                } else {
                    float s0 = v0 * inv_nm1 + ((r == c0)     ? EPS : 0.f);
                    float s1 = v1 * inv_nm1 + ((r == c0 + 1) ? EPS : 0.f);
                    o.x = (1.f - MOMENTUM) * Eg[off] + MOMENTUM * s0;
                    o.y = (1.f - MOMENTUM) * Eg[off + 1] + MOMENTUM * s1;
                }
                *(float2*)(C + off) = o;
                if (TRI && mirror) {
                    C[(size_t)c0 * N + r]       = o.x;
                    C[(size_t)(c0 + 1) * N + r] = o.y;
                }
            }
        }
    }
}

// ---------------- host launcher ----------------
extern "C" void kernel_launch(void* const* d_in, const int* in_sizes, int n_in,
                              void* d_out, int out_size) {
    const float* x  = (const float*)d_in[0];
    const float* rm = (const float*)d_in[1];
    const float* rc = (const float*)d_in[2];
    float* out = (float*)d_out;

    float *xn, *part, *sigma, *P, *Q, *T1, *T2, *meanp, *mean, *invtr, *rstr;
    cudaGetSymbolAddress((void**)&xn,    g_xn);
    cudaGetSymbolAddress((void**)&part,  g_part);
    cudaGetSymbolAddress((void**)&sigma, g_sigma);
    cudaGetSymbolAddress((void**)&P,     g_P);
    cudaGetSymbolAddress((void**)&Q,     g_Q);
    cudaGetSymbolAddress((void**)&T1,    g_T1);
    cudaGetSymbolAddress((void**)&T2,    g_T2);
    cudaGetSymbolAddress((void**)&meanp, g_meanp);
    cudaGetSymbolAddress((void**)&mean,  g_mean);
    cudaGetSymbolAddress((void**)&invtr, g_invtr);
    cudaGetSymbolAddress((void**)&rstr,  g_rstr);

    static bool attr_set = false;
    if (!attr_set) {
        cudaFuncSetAttribute(gemm_bf16x3_kernel<0,0,0,0>,
            cudaFuncAttributeMaxDynamicSharedMemorySize, GEMM_SMEM_TOTAL);
        cudaFuncSetAttribute(gemm_bf16x3_kernel<0,1,0,0>,
            cudaFuncAttributeMaxDynamicSharedMemorySize, GEMM_SMEM_TOTAL);
        cudaFuncSetAttribute(gemm_bf16x3_kernel<1,1,0,1>,
            cudaFuncAttributeMaxDynamicSharedMemorySize, GEMM_SMEM_TOTAL);
        cudaFuncSetAttribute(gemm_bf16x3_kernel<0,1,1,0>,
            cudaFuncAttributeMaxDynamicSharedMemorySize, GEMM_SMEM_TOTAL);
        attr_set = true;
    }

    const size_t FF = (size_t)F_ * F_;
    const size_t SF = (size_t)S_ * F_;

    // 1. blended mean (two-phase, full-chip parallel)
    mean_p1_kernel<<<dim3(16, B_), F_>>>(x, meanp);
    mean_p2_kernel<<<B_, F_>>>(meanp, rm, mean);
    // 2. xn = x - m
    xn_kernel<<<(unsigned)((size_t)B_ * SF / 4 / 256), 256>>>(x, mean, xn);
    // 3. SYRK K-split x4: part[q] = xn[512q:512q+512]^T @ xn[...]   (triangular)
    gemm_bf16x3_kernel<1,1,0,1><<<dim3(10, 4, B_), 256, GEMM_SMEM_TOTAL>>>(
        xn, xn, part, nullptr, nullptr, nullptr, F_, F_, 512, 0, SF, SF, FF,
        nullptr, nullptr, nullptr);
    // 3b. sigma = 0.9*rc + 0.1*(sum(part)/(S-1) + eps*I)
    reduce_sigma_kernel<<<(unsigned)((size_t)B_ * FF / 4 / 256), 256>>>(part, rc, sigma);
    // 4. trace
    trace_kernel<<<B_, F_>>>(sigma, invtr, rstr);
    // 5. P1 = 1.5I - 0.5 sigma/tr
    initp_kernel<<<(unsigned)((size_t)B_ * FF / 256), 256>>>(sigma, invtr, P);

    // 6. NS iterations 2..4:  P' = 1.5P - 0.5/tr * (P^2)*(P sigma)
    //    T1 = P*P and T2 = P*sigma are independent -> one paired launch.
    float* Pin = P;
    float* Pout = Q;
    for (int it = 0; it < 3; it++) {
        gemm_bf16x3_kernel<0,1,1,0><<<dim3(20, 1, B_), 256, GEMM_SMEM_TOTAL>>>(
            Pin, Pin, T1, nullptr, nullptr, nullptr, F_, F_, F_, 0, FF, FF, FF,
            Pin, sigma, T2);
        gemm_bf16x3_kernel<0,1,0,0><<<dim3(10, 1, B_), 256, GEMM_SMEM_TOTAL>>>(
            T1, T2, Pout, Pin, nullptr, invtr, F_, F_, F_, 1, FF, FF, FF,
            nullptr, nullptr, nullptr);
        float* tmp = Pin; Pin = Pout; Pout = tmp;
    }

    // 7. out = (xn @ P) * rsqrt(tr)
    gemm_bf16x3_kernel<0,0,0,0><<<dim3(4, 16, B_), 256, GEMM_SMEM_TOTAL>>>(
        xn, Pin, out, nullptr, nullptr, rstr, S_, F_, F_, 2, SF, FF, SF,
        nullptr, nullptr, nullptr);
}